// round 5
// baseline (speedup 1.0000x reference)
#include <cuda_runtime.h>

// ---------------------------------------------------------------------------
// SkinDeformNet: linear blend skinning.
// Kernel A (rig): Rodrigues + kinematic chain -> Rs, Jt, compact A12 scratch.
// Kernel B (pts): 1 pt/thread; w[24] loaded upfront (one DRAM-latency
//                 exposure, MLP=6); A12 broadcast from smem; row 3 of T is
//                 constant; <=64 regs (4 CTAs/SM, occ ~50%).
// ---------------------------------------------------------------------------

#define MAX_B  64
#define NB_MAX 3
#define PTS_BLOCK 256

typedef unsigned long long ull;

// compact A: 12 floats (3x4 rows) per joint => 288 floats (1152 B) per batch
__device__ __align__(16) float g_A[MAX_B * 24 * 12];

__device__ const int c_par[24]   = {-1,0,0,0,1,2,3,4,5,6,7,8,9,9,9,12,13,14,16,17,18,19,20,21};
__device__ const int c_depth[24] = { 0,1,1,1,2,2,2,3,3,3,4,4,4,4,4, 5, 5, 5, 6, 6, 7, 7, 8, 8};

// ============================= Kernel A: rig ===============================
__global__ void rig_kernel(const float* __restrict__ Js,
                           const float* __restrict__ poses,
                           float* __restrict__ outRs,
                           float* __restrict__ outJt)
{
    const int b = blockIdx.x;
    const int j = threadIdx.x;      // 32 threads, j<24 active

    __shared__ float sJ[24][3];
    __shared__ float sRes[24][12];  // 3x4 rows of the chained transform

    float R[9];
    if (j < 24) {
        float rx = poses[b*72 + j*3 + 0];
        float ry = poses[b*72 + j*3 + 1];
        float rz = poses[b*72 + j*3 + 2];
        float ang = sqrtf(rx*rx + ry*ry + rz*rz) + 1e-8f;
        float inv = 1.0f / ang;
        float x = rx*inv, y = ry*inv, z = rz*inv;
        float s = sinf(ang), c = cosf(ang);
        float o = 1.0f - c;
        R[0] = 1.0f - o*(y*y + z*z);
        R[1] = -s*z + o*(x*y);
        R[2] =  s*y + o*(x*z);
        R[3] =  s*z + o*(x*y);
        R[4] = 1.0f - o*(x*x + z*z);
        R[5] = -s*x + o*(y*z);
        R[6] = -s*y + o*(x*z);
        R[7] =  s*x + o*(y*z);
        R[8] = 1.0f - o*(x*x + y*y);
        #pragma unroll
        for (int i = 0; i < 9; i++) outRs[b*216 + j*9 + i] = R[i];
        sJ[j][0] = Js[b*72 + j*3 + 0];
        sJ[j][1] = Js[b*72 + j*3 + 1];
        sJ[j][2] = Js[b*72 + j*3 + 2];
    }
    __syncthreads();

    float res[12];
    const int dj = (j < 24) ? c_depth[j] : -1;
    for (int lv = 0; lv < 9; lv++) {
        if (dj == lv) {
            if (j == 0) {
                res[0]=R[0]; res[1]=R[1]; res[2] =R[2]; res[3] =sJ[0][0];
                res[4]=R[3]; res[5]=R[4]; res[6] =R[5]; res[7] =sJ[0][1];
                res[8]=R[6]; res[9]=R[7]; res[10]=R[8]; res[11]=sJ[0][2];
            } else {
                int p = c_par[j];
                float tx = sJ[j][0]-sJ[p][0], ty = sJ[j][1]-sJ[p][1], tz = sJ[j][2]-sJ[p][2];
                #pragma unroll
                for (int r = 0; r < 3; r++) {
                    float p0 = sRes[p][r*4+0], p1 = sRes[p][r*4+1];
                    float p2 = sRes[p][r*4+2], p3 = sRes[p][r*4+3];
                    res[r*4+0] = p0*R[0] + p1*R[3] + p2*R[6];
                    res[r*4+1] = p0*R[1] + p1*R[4] + p2*R[7];
                    res[r*4+2] = p0*R[2] + p1*R[5] + p2*R[8];
                    res[r*4+3] = p0*tx   + p1*ty   + p2*tz + p3;
                }
            }
            #pragma unroll
            for (int i = 0; i < 12; i++) sRes[j][i] = res[i];
        }
        __syncthreads();
    }

    if (j < 24) {
        float Jx = sJ[j][0], Jy = sJ[j][1], Jz = sJ[j][2];
        float* A = &g_A[(b*24 + j) * 12];
        #pragma unroll
        for (int r = 0; r < 3; r++) {
            A[r*4+0] = res[r*4+0];
            A[r*4+1] = res[r*4+1];
            A[r*4+2] = res[r*4+2];
            A[r*4+3] = res[r*4+3] - (res[r*4+0]*Jx + res[r*4+1]*Jy + res[r*4+2]*Jz);
            outJt[b*72 + j*3 + r] = res[r*4+3];
        }
    }
}

// ============================= Kernel B: points ============================
__device__ __forceinline__ ull fma2(ull a, ull b, ull c)
{
    ull d;
    asm("fma.rn.f32x2 %0, %1, %2, %3;" : "=l"(d) : "l"(a), "l"(b), "l"(c));
    return d;
}

__device__ __forceinline__ ull pack2(float v)
{
    ull d;
    asm("mov.b64 %0, {%1, %2};" : "=l"(d) : "f"(v), "f"(v));
    return d;
}

// Accumulate one point's T over 24 joints from an A stream (smem or global).
// Weights are fully register-resident; loads are compiler-visible so ptxas
// can batch the 12 LDS/LDG of each 4-joint group (high MLP).
__device__ __forceinline__ void lbs_accum(const ulonglong2* __restrict__ Ap,
                                          const float4* __restrict__ wv,
                                          ull* acc)
{
    #pragma unroll 1
    for (int j = 0; j < 6; j++) {
        const float4 cw = wv[j];
        const float cc[4] = {cw.x, cw.y, cw.z, cw.w};
        const ulonglong2* Aj = Ap + j * 12;
        #pragma unroll
        for (int c = 0; c < 4; c++) {
            ulonglong2 p0 = Aj[c*3 + 0];
            ulonglong2 p1 = Aj[c*3 + 1];
            ulonglong2 p2 = Aj[c*3 + 2];
            ull ww = pack2(cc[c]);
            acc[0] = fma2(ww, p0.x, acc[0]);
            acc[1] = fma2(ww, p0.y, acc[1]);
            acc[2] = fma2(ww, p1.x, acc[2]);
            acc[3] = fma2(ww, p1.y, acc[3]);
            acc[4] = fma2(ww, p2.x, acc[4]);
            acc[5] = fma2(ww, p2.y, acc[5]);
        }
    }
}

__global__ void __launch_bounds__(PTS_BLOCK, 4)
pts_kernel(const float* __restrict__ ps,
           const float* __restrict__ ws,
           const void*  __restrict__ batch_raw,
           float* __restrict__ outP,
           float* __restrict__ outT,
           int N)
{
    __shared__ __align__(16) ull sA[NB_MAX * 144];   // 144 ull = 1152 B per batch
    __shared__ int s_info[3];                        // blo, nb, is64

    const int tid  = threadIdx.x;
    const int base = blockIdx.x * PTS_BLOCK;

    const int*       b32 = (const int*)batch_raw;
    const long long* b64 = (const long long*)batch_raw;

    if (tid == 0) {
        // dtype probe: batch sorted, max ~B-1 (>0). If int64, the last 32-bit
        // word is a (zero) high half; if int32 it is the (nonzero) max value.
        int is64 = (b32[N - 1] == 0) ? 1 : 0;
        int last = base + PTS_BLOCK - 1; if (last > N - 1) last = N - 1;
        int blo = is64 ? (int)b64[base] : b32[base];
        int bhi = is64 ? (int)b64[last] : b32[last];
        int nb  = bhi - blo + 1; if (nb > NB_MAX) nb = NB_MAX;
        s_info[0] = blo; s_info[1] = nb; s_info[2] = is64;
    }
    __syncthreads();
    const int blo  = s_info[0];
    const int nb   = s_info[1];
    const int is64 = s_info[2];

    // cooperative stage of A12 rows [blo, blo+nb) into smem
    {
        const ulonglong2* src = reinterpret_cast<const ulonglong2*>(g_A) + blo * 72;
        ulonglong2* dst = reinterpret_cast<ulonglong2*>(sA);
        for (int i = tid; i < nb * 72; i += PTS_BLOCK) dst[i] = __ldg(src + i);
    }
    __syncthreads();

    const int n = base + tid;
    if (n >= N) return;

    const int b = is64 ? (int)b64[n] : b32[n];

    // all 24 weights upfront: 6 independent LDG.128 -> one latency exposure
    float4 wv[6];
    const float4* wsv = reinterpret_cast<const float4*>(ws + (size_t)n * 24);
    #pragma unroll
    for (int i = 0; i < 6; i++) wv[i] = wsv[i];

    ull acc[6];
    #pragma unroll
    for (int i = 0; i < 6; i++) acc[i] = 0ull;

    const int local = b - blo;
    if ((unsigned)local < (unsigned)nb) {
        lbs_accum(reinterpret_cast<const ulonglong2*>(sA + local * 144), wv, acc);
    } else {
        lbs_accum(reinterpret_cast<const ulonglong2*>(g_A + (size_t)b * 288), wv, acc);
    }

    // unpack T rows
    float t[12];
    #pragma unroll
    for (int i = 0; i < 6; i++)
        asm("mov.b64 {%0, %1}, %2;" : "=f"(t[2*i]), "=f"(t[2*i+1]) : "l"(acc[i]));

    float4* Tp = reinterpret_cast<float4*>(outT + (size_t)n * 16);
    Tp[0] = make_float4(t[0], t[1], t[2],  t[3]);
    Tp[1] = make_float4(t[4], t[5], t[6],  t[7]);
    Tp[2] = make_float4(t[8], t[9], t[10], t[11]);
    Tp[3] = make_float4(0.0f, 0.0f, 0.0f,  1.0f);

    const float px = ps[(size_t)n*3 + 0];
    const float py = ps[(size_t)n*3 + 1];
    const float pz = ps[(size_t)n*3 + 2];
    outP[(size_t)n*3 + 0] = t[0]*px + t[1]*py + t[2] *pz + t[3];
    outP[(size_t)n*3 + 1] = t[4]*px + t[5]*py + t[6] *pz + t[7];
    outP[(size_t)n*3 + 2] = t[8]*px + t[9]*py + t[10]*pz + t[11];
}

// =============================== launch ====================================
extern "C" void kernel_launch(void* const* d_in, const int* in_sizes, int n_in,
                              void* d_out, int out_size)
{
    const float* ps    = (const float*)d_in[0];
    const float* Js    = (const float*)d_in[1];
    const float* ws    = (const float*)d_in[2];
    const float* poses = (const float*)d_in[3];
    const void*  batch = d_in[4];

    const int N = in_sizes[0] / 3;
    int B = in_sizes[3] / 72;
    if (B > MAX_B) B = MAX_B;

    float* out   = (float*)d_out;
    float* outP  = out;                                  // N*3
    float* outT  = outP + (size_t)N * 3;                 // N*16
    float* outRs = outT + (size_t)N * 16;                // B*216
    float* outJt = outRs + (size_t)B * 216;              // B*72

    rig_kernel<<<B, 32>>>(Js, poses, outRs, outJt);

    const int blocks = (N + PTS_BLOCK - 1) / PTS_BLOCK;
    pts_kernel<<<blocks, PTS_BLOCK>>>(ps, ws, batch, outP, outT, N);
}

// round 6
// speedup vs baseline: 1.1910x; 1.1910x over previous
#include <cuda_runtime.h>

// ---------------------------------------------------------------------------
// SkinDeformNet: linear blend skinning.
// Kernel A (rig): Rodrigues + kinematic chain -> Rs, Jt, compact A12 scratch.
// Kernel B (pts): 1 pt/thread; ws/ps/batch loads issued BEFORE the staging
//                 barrier (latency overlapped); A12 broadcast from smem
//                 (crossbar-bound at ~9 cyc/pt); row 3 of T constant.
// ---------------------------------------------------------------------------

#define MAX_B  64
#define NB_MAX 4
#define PTS_BLOCK 256

typedef unsigned long long ull;

// compact A: 12 floats (3x4 rows) per joint => 288 floats (1152 B) per batch
__device__ __align__(16) float g_A[MAX_B * 24 * 12];

__device__ const int c_par[24]   = {-1,0,0,0,1,2,3,4,5,6,7,8,9,9,9,12,13,14,16,17,18,19,20,21};
__device__ const int c_depth[24] = { 0,1,1,1,2,2,2,3,3,3,4,4,4,4,4, 5, 5, 5, 6, 6, 7, 7, 8, 8};

// ============================= Kernel A: rig ===============================
__global__ void rig_kernel(const float* __restrict__ Js,
                           const float* __restrict__ poses,
                           float* __restrict__ outRs,
                           float* __restrict__ outJt)
{
    const int b = blockIdx.x;
    const int j = threadIdx.x;      // 32 threads, j<24 active

    __shared__ float sJ[24][3];
    __shared__ float sRes[24][12];  // 3x4 rows of the chained transform

    float R[9];
    if (j < 24) {
        float rx = poses[b*72 + j*3 + 0];
        float ry = poses[b*72 + j*3 + 1];
        float rz = poses[b*72 + j*3 + 2];
        float ang = sqrtf(rx*rx + ry*ry + rz*rz) + 1e-8f;
        float inv = 1.0f / ang;
        float x = rx*inv, y = ry*inv, z = rz*inv;
        float s = sinf(ang), c = cosf(ang);
        float o = 1.0f - c;
        R[0] = 1.0f - o*(y*y + z*z);
        R[1] = -s*z + o*(x*y);
        R[2] =  s*y + o*(x*z);
        R[3] =  s*z + o*(x*y);
        R[4] = 1.0f - o*(x*x + z*z);
        R[5] = -s*x + o*(y*z);
        R[6] = -s*y + o*(x*z);
        R[7] =  s*x + o*(y*z);
        R[8] = 1.0f - o*(x*x + y*y);
        #pragma unroll
        for (int i = 0; i < 9; i++) outRs[b*216 + j*9 + i] = R[i];
        sJ[j][0] = Js[b*72 + j*3 + 0];
        sJ[j][1] = Js[b*72 + j*3 + 1];
        sJ[j][2] = Js[b*72 + j*3 + 2];
    }
    __syncthreads();

    float res[12];
    const int dj = (j < 24) ? c_depth[j] : -1;
    for (int lv = 0; lv < 9; lv++) {
        if (dj == lv) {
            if (j == 0) {
                res[0]=R[0]; res[1]=R[1]; res[2] =R[2]; res[3] =sJ[0][0];
                res[4]=R[3]; res[5]=R[4]; res[6] =R[5]; res[7] =sJ[0][1];
                res[8]=R[6]; res[9]=R[7]; res[10]=R[8]; res[11]=sJ[0][2];
            } else {
                int p = c_par[j];
                float tx = sJ[j][0]-sJ[p][0], ty = sJ[j][1]-sJ[p][1], tz = sJ[j][2]-sJ[p][2];
                #pragma unroll
                for (int r = 0; r < 3; r++) {
                    float p0 = sRes[p][r*4+0], p1 = sRes[p][r*4+1];
                    float p2 = sRes[p][r*4+2], p3 = sRes[p][r*4+3];
                    res[r*4+0] = p0*R[0] + p1*R[3] + p2*R[6];
                    res[r*4+1] = p0*R[1] + p1*R[4] + p2*R[7];
                    res[r*4+2] = p0*R[2] + p1*R[5] + p2*R[8];
                    res[r*4+3] = p0*tx   + p1*ty   + p2*tz + p3;
                }
            }
            #pragma unroll
            for (int i = 0; i < 12; i++) sRes[j][i] = res[i];
        }
        __syncthreads();
    }

    if (j < 24) {
        float Jx = sJ[j][0], Jy = sJ[j][1], Jz = sJ[j][2];
        float* A = &g_A[(b*24 + j) * 12];
        #pragma unroll
        for (int r = 0; r < 3; r++) {
            A[r*4+0] = res[r*4+0];
            A[r*4+1] = res[r*4+1];
            A[r*4+2] = res[r*4+2];
            A[r*4+3] = res[r*4+3] - (res[r*4+0]*Jx + res[r*4+1]*Jy + res[r*4+2]*Jz);
            outJt[b*72 + j*3 + r] = res[r*4+3];
        }
    }
}

// ============================= Kernel B: points ============================
__device__ __forceinline__ ull fma2(ull a, ull b, ull c)
{
    ull d;
    asm("fma.rn.f32x2 %0, %1, %2, %3;" : "=l"(d) : "l"(a), "l"(b), "l"(c));
    return d;
}

__device__ __forceinline__ ull pack2(float v)
{
    ull d;
    asm("mov.b64 %0, {%1, %2};" : "=l"(d) : "f"(v), "f"(v));
    return d;
}

// Accumulate one point's T over 24 joints from an A stream (smem or global).
__device__ __forceinline__ void lbs_accum(const ulonglong2* __restrict__ Ap,
                                          const float* __restrict__ w,
                                          ull* acc)
{
    #pragma unroll
    for (int k = 0; k < 24; k++) {
        ulonglong2 p0 = Ap[k*3 + 0];
        ulonglong2 p1 = Ap[k*3 + 1];
        ulonglong2 p2 = Ap[k*3 + 2];
        ull ww = pack2(w[k]);
        acc[0] = fma2(ww, p0.x, acc[0]);
        acc[1] = fma2(ww, p0.y, acc[1]);
        acc[2] = fma2(ww, p1.x, acc[2]);
        acc[3] = fma2(ww, p1.y, acc[3]);
        acc[4] = fma2(ww, p2.x, acc[4]);
        acc[5] = fma2(ww, p2.y, acc[5]);
    }
}

__global__ void __launch_bounds__(PTS_BLOCK, 4)
pts_kernel(const float* __restrict__ ps,
           const float* __restrict__ ws,
           const void*  __restrict__ batch_raw,
           float* __restrict__ outP,
           float* __restrict__ outT,
           int N)
{
    __shared__ __align__(16) ull sA[NB_MAX * 144];   // 144 ull = 1152 B per batch
    __shared__ int s_blo, s_bhi;

    const int tid  = threadIdx.x;
    const int base = blockIdx.x * PTS_BLOCK;
    const int n    = base + tid;
    const int nc   = (n < N) ? n : (N - 1);           // clamped (all threads stage)

    const int*       b32 = (const int*)batch_raw;
    const long long* b64 = (const long long*)batch_raw;

    // dtype probe (L2-hot, warp-dedup'd): batch sorted, max = B-1 > 0. If
    // int64, the last 32-bit word is a zero high-half; if int32, it's B-1.
    const bool is64 = (__ldg(b32 + (N - 1)) == 0);
    const int  b    = is64 ? (int)__ldg(b64 + nc) : __ldg(b32 + nc);

    // ---- prefetch the streaming inputs BEFORE the barrier (overlap DRAM) ----
    float w[24];
    {
        const float4* wsv = reinterpret_cast<const float4*>(ws + (size_t)nc * 24);
        #pragma unroll
        for (int i = 0; i < 6; i++) {
            float4 v = __ldg(wsv + i);
            w[i*4+0] = v.x; w[i*4+1] = v.y; w[i*4+2] = v.z; w[i*4+3] = v.w;
        }
    }
    const float px = __ldg(ps + (size_t)nc*3 + 0);
    const float py = __ldg(ps + (size_t)nc*3 + 1);
    const float pz = __ldg(ps + (size_t)nc*3 + 2);

    // publish block batch window from registers (no extra loads, no serial chain)
    const int last_tid = (base + PTS_BLOCK - 1 < N) ? (PTS_BLOCK - 1) : (N - 1 - base);
    if (tid == 0)        s_blo = b;
    if (tid == last_tid) s_bhi = b;
    __syncthreads();

    const int blo = s_blo;
    int nb = s_bhi - blo + 1;
    if (nb > NB_MAX) nb = NB_MAX;

    // cooperative stage of A12 rows [blo, blo+nb) into smem
    {
        const ulonglong2* src = reinterpret_cast<const ulonglong2*>(g_A) + blo * 72;
        ulonglong2* dst = reinterpret_cast<ulonglong2*>(sA);
        for (int i = tid; i < nb * 72; i += PTS_BLOCK) dst[i] = __ldg(src + i);
    }
    __syncthreads();

    if (n >= N) return;

    ull acc[6];
    #pragma unroll
    for (int i = 0; i < 6; i++) acc[i] = 0ull;

    const int local = b - blo;
    if ((unsigned)local < (unsigned)nb) {
        lbs_accum(reinterpret_cast<const ulonglong2*>(sA + local * 144), w, acc);
    } else {
        lbs_accum(reinterpret_cast<const ulonglong2*>(g_A + (size_t)b * 288), w, acc);
    }

    // unpack T rows
    float t[12];
    #pragma unroll
    for (int i = 0; i < 6; i++)
        asm("mov.b64 {%0, %1}, %2;" : "=f"(t[2*i]), "=f"(t[2*i+1]) : "l"(acc[i]));

    float4* Tp = reinterpret_cast<float4*>(outT + (size_t)n * 16);
    Tp[0] = make_float4(t[0], t[1], t[2],  t[3]);
    Tp[1] = make_float4(t[4], t[5], t[6],  t[7]);
    Tp[2] = make_float4(t[8], t[9], t[10], t[11]);
    Tp[3] = make_float4(0.0f, 0.0f, 0.0f,  1.0f);

    outP[(size_t)n*3 + 0] = t[0]*px + t[1]*py + t[2] *pz + t[3];
    outP[(size_t)n*3 + 1] = t[4]*px + t[5]*py + t[6] *pz + t[7];
    outP[(size_t)n*3 + 2] = t[8]*px + t[9]*py + t[10]*pz + t[11];
}

// =============================== launch ====================================
extern "C" void kernel_launch(void* const* d_in, const int* in_sizes, int n_in,
                              void* d_out, int out_size)
{
    const float* ps    = (const float*)d_in[0];
    const float* Js    = (const float*)d_in[1];
    const float* ws    = (const float*)d_in[2];
    const float* poses = (const float*)d_in[3];
    const void*  batch = d_in[4];

    const int N = in_sizes[0] / 3;
    int B = in_sizes[3] / 72;
    if (B > MAX_B) B = MAX_B;

    float* out   = (float*)d_out;
    float* outP  = out;                                  // N*3
    float* outT  = outP + (size_t)N * 3;                 // N*16
    float* outRs = outT + (size_t)N * 16;                // B*216
    float* outJt = outRs + (size_t)B * 216;              // B*72

    rig_kernel<<<B, 32>>>(Js, poses, outRs, outJt);

    const int blocks = (N + PTS_BLOCK - 1) / PTS_BLOCK;
    pts_kernel<<<blocks, PTS_BLOCK>>>(ps, ws, batch, outP, outT, N);
}